// round 16
// baseline (speedup 1.0000x reference)
#include <cuda_runtime.h>
#include <cuda_fp16.h>
#include <math.h>
#include <stdint.h>

#define B_ROWS 4096
#define N_COLS 4096
#define D_K    512

#define TILE_M 128
#define TILE_N 64
#define KC     32                  // per chunk: two 16-col sub-arrays
#define NCHUNK (D_K / KC)          // 16
#define NSTAGE 4

// Each 16-col sub-array uses the PROVEN layout: rows of 16 halves padded to
// 24 halves (48 B) -> 16B-aligned cp.async segs, 12-word-stride fragment LDS.
#define ASUB_B   (128 * 48)        // 6144 bytes per A sub-array
#define BSUB_B   (64 * 48)         // 3072 bytes per B sub-array
#define OFF_A0   0
#define OFF_A1   ASUB_B
#define OFF_B0   (2 * ASUB_B)
#define OFF_B1   (2 * ASUB_B + BSUB_B)
#define STAGE_B  (2 * ASUB_B + 2 * BSUB_B)   // 18432
#define SMEM_BYTES (NSTAGE * STAGE_B)        // 73728 (x2 CTAs = 144KB < 228KB)

#define CAP   32                   // candidates per row (warp-local)
#define GCAP  16                   // qualifying 32-col groups per row
#define NGRP  (N_COLS / 32)        // 128 groups per row

// ---------------- scratch (__device__ globals; no allocation allowed) -------
// g_whmax2/g_wlmax2: zero-initialized at module load; atomicMax with
// deterministic identical values every run -> idempotent, no re-init needed.
__device__ __half g_xh[B_ROWS * D_K];
__device__ __half g_wh[N_COLS * D_K];
__device__ float g_xsq[B_ROWS];
__device__ float g_wsq[N_COLS];
__device__ float g_xl2[B_ROWS];        // ||xl||^2 per row
__device__ float g_xh2[B_ROWS];        // ||xh||^2 per row
__device__ unsigned int g_whmax2;      // max_c ||wh_c||^2 (float bits)
__device__ unsigned int g_wlmax2;      // max_c ||wl_c||^2 (float bits)
__device__ unsigned long long g_best[B_ROWS];
__device__ __half g_off[(size_t)B_ROWS * N_COLS];   // 33.5 MB approx offsets
__device__ float g_gmin[B_ROWS * NGRP];             // 2 MB per-group minima

// ---------------- PTX helpers ----------------------------------------------
__device__ __forceinline__ uint32_t smem_u32(const void* p) {
    uint32_t a;
    asm("{ .reg .u64 t; cvta.to.shared.u64 t, %1; cvt.u32.u64 %0, t; }"
        : "=r"(a) : "l"(p));
    return a;
}
#define CP16(sa, ga) \
    asm volatile("cp.async.cg.shared.global [%0], [%1], 16;" \
                 :: "r"(sa), "l"(ga) : "memory")
#define CP_COMMIT()  asm volatile("cp.async.commit_group;" ::: "memory")
#define CP_WAIT2()   asm volatile("cp.async.wait_group 2;" ::: "memory")
#define CP_WAIT1()   asm volatile("cp.async.wait_group 1;" ::: "memory")
#define CP_WAIT0()   asm volatile("cp.async.wait_group 0;" ::: "memory")

__device__ __forceinline__ void mma16816(float* d, const uint32_t* a,
                                         const uint32_t* b) {
    asm volatile(
        "mma.sync.aligned.m16n8k16.row.col.f32.f16.f16.f32 "
        "{%0,%1,%2,%3}, {%4,%5,%6,%7}, {%8,%9}, {%0,%1,%2,%3};"
        : "+f"(d[0]), "+f"(d[1]), "+f"(d[2]), "+f"(d[3])
        : "r"(a[0]), "r"(a[1]), "r"(a[2]), "r"(a[3]), "r"(b[0]), "r"(b[1]));
}

// ---------------------------------------------------------------------------
// Kernel 0: fp16 hi plane + norms. One warp per row (x rows, then w rows).
// w-blocks reduce their 8 warps' norm maxima in smem -> ONE atomicMax pair
// per block (8x fewer same-address L2 atomics).
// ---------------------------------------------------------------------------
__global__ void prep_kernel(const float* __restrict__ x,
                            const float* __restrict__ w) {
    __shared__ float s_sh[8], s_sl[8];
    int warp = (blockIdx.x * blockDim.x + threadIdx.x) >> 5;
    int wib  = (threadIdx.x >> 5);   // warp in block 0..7
    int lane = threadIdx.x & 31;
    if (warp >= B_ROWS + N_COLS) return;   // never taken with exact grid
    bool isx = (warp < B_ROWS);
    int row = isx ? warp : warp - B_ROWS;
    const float* src = isx ? (x + (size_t)row * D_K) : (w + (size_t)row * D_K);
    __half* dh = isx ? (g_xh + (size_t)row * D_K) : (g_wh + (size_t)row * D_K);

    float s = 0.f, sl = 0.f, sh = 0.f;
    #pragma unroll
    for (int k = lane * 4; k < D_K; k += 128) {
        float4 v = *reinterpret_cast<const float4*>(src + k);
        s += v.x * v.x + v.y * v.y + v.z * v.z + v.w * v.w;
        __half2 h01 = __floats2half2_rn(v.x, v.y);
        __half2 h23 = __floats2half2_rn(v.z, v.w);
        float2 f01 = __half22float2(h01);
        float2 f23 = __half22float2(h23);
        sh += f01.x * f01.x + f01.y * f01.y + f23.x * f23.x + f23.y * f23.y;
        float e0 = v.x - f01.x, e1 = v.y - f01.y;
        float e2 = v.z - f23.x, e3 = v.w - f23.y;
        sl += e0 * e0 + e1 * e1 + e2 * e2 + e3 * e3;
        __half2 hp[2] = { h01, h23 };
        *reinterpret_cast<uint2*>(dh + k) = *reinterpret_cast<uint2*>(hp);
    }
    #pragma unroll
    for (int o = 16; o; o >>= 1) {
        s  += __shfl_xor_sync(0xffffffffu, s, o);
        sl += __shfl_xor_sync(0xffffffffu, sl, o);
        sh += __shfl_xor_sync(0xffffffffu, sh, o);
    }
    if (lane == 0) {
        if (isx) {
            g_xsq[row] = s; g_xl2[row] = sl; g_xh2[row] = sh;
            g_best[row] = 0xFFFFFFFFFFFFFFFFull;
        } else {
            g_wsq[row] = s;
            s_sh[wib] = sh;
            s_sl[wib] = sl;
        }
    }
    if (!isx) {
        __syncthreads();
        if (threadIdx.x == 0) {
            float mh = s_sh[0], ml = s_sl[0];
            #pragma unroll
            for (int i = 1; i < 8; i++) {
                mh = fmaxf(mh, s_sh[i]);
                ml = fmaxf(ml, s_sl[i]);
            }
            atomicMax(&g_whmax2, __float_as_uint(mh));  // non-neg: bit order ok
            atomicMax(&g_wlmax2, __float_as_uint(ml));
        }
    }
}

// ---------------------------------------------------------------------------
// Kernel 1: fp16 hh-only GEMM (approx) + fp16 offset store + group minima.
// TILE 128x64 -> 2048 CTAs (6.74 waves: tail waste ~2.5us vs ~11us at
// 128x128). KC=32 chunks stored as TWO 16-col sub-arrays, each in the
// PROVEN 48B-row layout -> same cp.async store & LDS conflict profile as
// the 94.3us kernel, and 16 MMAs per __syncthreads (same ratio).
// 8 warps as 4(m) x 2(n); warp tile 32x32. 4-stage pipeline, prefetch
// distance 2 -> one sync per chunk race-free ((i-1)%4 != (i+2)%4).
// ---------------------------------------------------------------------------
__global__ __launch_bounds__(256, 2)
void som_mma_kernel() {
    extern __shared__ char smem[];
    const uint32_t sb = smem_u32(smem);
    const int tid  = threadIdx.x;
    const int wid  = tid >> 5;
    const int lane = tid & 31;
    const int gid  = lane >> 2;
    const int tg   = lane & 3;
    const int wm   = wid & 3;        // m warp 0..3 (32 rows each)
    const int wn   = wid >> 2;       // n warp 0..1 (32 cols each)
    const int m0 = blockIdx.x * TILE_M;
    const int n0 = blockIdx.y * TILE_N;

    float acc[2][4][4];
    #pragma unroll
    for (int mi = 0; mi < 2; mi++)
        #pragma unroll
        for (int ni = 0; ni < 4; ni++)
            #pragma unroll
            for (int c = 0; c < 4; c++) acc[mi][ni][c] = 0.f;

    // A: per sub-array 128 rows x 2 segs = 256 slots (1/thread);
    // B: 2 sub x 64 rows x 2 segs = 256 slots (1/thread).
    const int arow = tid >> 1, aseg = tid & 1;
    const uint32_t aso = (uint32_t)(arow * 48 + aseg * 16);
    const int bsub = tid >> 7, brow = (tid & 127) >> 1, bseg = tid & 1;
    const uint32_t bso = (uint32_t)(brow * 48 + bseg * 16);

    auto load_chunk = [&](int kc) {
        const int kb = kc * KC;
        const uint32_t stage = sb + (uint32_t)((kc % NSTAGE) * STAGE_B);
        CP16(stage + OFF_A0 + aso,
             (const void*)(g_xh + (size_t)(m0 + arow) * D_K + kb + aseg * 8));
        CP16(stage + OFF_A1 + aso,
             (const void*)(g_xh + (size_t)(m0 + arow) * D_K + kb + 16 + aseg * 8));
        CP16(stage + OFF_B0 + (uint32_t)(bsub * BSUB_B) + bso,
             (const void*)(g_wh + (size_t)(n0 + brow) * D_K + kb + bsub * 16 + bseg * 8));
        CP_COMMIT();
    };

    load_chunk(0); load_chunk(1);

    for (int i = 0; i < NCHUNK; i++) {
        if (i + 2 < NCHUNK) { load_chunk(i + 2); CP_WAIT2(); }
        else if (i + 1 < NCHUNK) { CP_WAIT1(); }
        else { CP_WAIT0(); }
        __syncthreads();

        const char* st = smem + (i % NSTAGE) * STAGE_B;
        #pragma unroll
        for (int ks = 0; ks < 2; ks++) {
            const uint32_t* sA = (const uint32_t*)(st + (ks ? OFF_A1 : OFF_A0));
            const uint32_t* sB = (const uint32_t*)(st + (ks ? OFF_B1 : OFF_B0));

            uint32_t bh[4][2];
            #pragma unroll
            for (int ni = 0; ni < 4; ni++) {
                int r = (wn * 32 + ni * 8 + gid) * 12 + tg;
                bh[ni][0] = sB[r]; bh[ni][1] = sB[r + 4];
            }
            #pragma unroll
            for (int mi = 0; mi < 2; mi++) {
                int r = (wm * 32 + mi * 16 + gid) * 12 + tg;
                uint32_t ah[4];
                ah[0] = sA[r];           ah[2] = sA[r + 4];
                ah[1] = sA[r + 96];      ah[3] = sA[r + 100];   // +8 rows
                #pragma unroll
                for (int ni = 0; ni < 4; ni++)
                    mma16816(acc[mi][ni], ah, bh[ni]);
            }
        }
    }

    // ---- epilogue: offsets to fp16, per-group min, per-row approx argmin --
    float ws[4][2];
    #pragma unroll
    for (int ni = 0; ni < 4; ni++) {
        int col = n0 + wn * 32 + ni * 8 + tg * 2;
        ws[ni][0] = g_wsq[col];
        ws[ni][1] = g_wsq[col + 1];
    }
    const int grp = (n0 >> 5) + wn;   // this warp's 32-col group index

    #pragma unroll
    for (int mi = 0; mi < 2; mi++) {
        #pragma unroll
        for (int h = 0; h < 2; h++) {
            const int row = m0 + wm * 32 + mi * 16 + gid + h * 8;
            const float xs = g_xsq[row];
            unsigned long long best = 0xFFFFFFFFFFFFFFFFull;
            #pragma unroll
            for (int ni = 0; ni < 4; ni++) {
                const int col = n0 + wn * 32 + ni * 8 + tg * 2;
                float off0 = 0.f, off1 = 0.f;
                #pragma unroll
                for (int c = 0; c < 2; c++) {
                    const float dot = acc[mi][ni][h * 2 + c];
                    float off = ws[ni][c] - 2.0f * dot;
                    if (c == 0) off0 = off; else off1 = off;
                    float v = xs + off;
                    unsigned long long u =
                        ((unsigned long long)__float_as_uint(v) << 32) |
                        (unsigned long long)(uint32_t)(col + c);
                    best = (u < best) ? u : best;
                }
                *reinterpret_cast<__half2*>(
                    g_off + (size_t)row * N_COLS + col) =
                    __floats2half2_rn(off0, off1);
            }
            unsigned long long o;
            o = __shfl_xor_sync(0xffffffffu, best, 1); best = (o < best) ? o : best;
            o = __shfl_xor_sync(0xffffffffu, best, 2); best = (o < best) ? o : best;
            if (tg == 0) {
                // exact fp32 min value over this warp's 32 cols for this row
                g_gmin[row * NGRP + grp] =
                    __uint_as_float((uint32_t)(best >> 32));
                atomicMin(&g_best[row], best);
            }
        }
    }
}

// ---------------------------------------------------------------------------
// Kernel 2: hierarchical warp-per-row screen + exact fp32 rescreen + output.
// Independent loads (x row, gmin, norms) hoisted to the top to overlap the
// threshold dependency chain.
// ---------------------------------------------------------------------------
__global__ __launch_bounds__(256)
void screen_kernel(const float* __restrict__ x, const float* __restrict__ w,
                   float* __restrict__ out) {
    const int wly  = threadIdx.x >> 5;          // warp in block 0..7
    const int lane = threadIdx.x & 31;
    const int r    = blockIdx.x * 8 + wly;      // row

    __shared__ int s_cand[8][CAP];
    __shared__ int s_cnt[8];
    __shared__ int s_grp[8][GCAP];
    __shared__ int s_gcnt[8];

    if (lane == 0) { s_cnt[wly] = 0; s_gcnt[wly] = 0; }

    // ---- independent loads first (overlap the threshold chain) -----------
    const float* xrow = x + (size_t)r * D_K;
    float4 xr[4];
    #pragma unroll
    for (int j = 0; j < 4; j++)
        xr[j] = *reinterpret_cast<const float4*>(xrow + lane * 16 + j * 4);
    float4 gm = *reinterpret_cast<const float4*>(g_gmin + r * NGRP + lane * 4);
    const float xs = g_xsq[r];
    const float xl2 = g_xl2[r];
    const float xh2 = g_xh2[r];
    const unsigned long long brow = g_best[r];
    const float whm2 = __uint_as_float(g_whmax2);
    const float wlm2 = __uint_as_float(g_wlmax2);
    __syncwarp();

    // threshold in VALUE space (all lanes redundantly; broadcast loads)
    const float minv = __uint_as_float((uint32_t)(brow >> 32));
    const float whm = sqrtf(whm2), wlm = sqrtf(wlm2);
    const float xln = sqrtf(xl2),  xhn = sqrtf(xh2);
    // |v_exact - v_approx| <= 2*(xl.wh + xh.wl + xl.wl), 1.5x safety,
    // +0.02 covers fp16 offset-storage quantization.
    const float e_v = 3.0f * (xln * whm + xhn * wlm + xln * wlm) + 0.02f;
    const float thrv = minv + 2.0f * e_v;

    // level 1: scan 128 exact group minima (float4 per lane)
    #pragma unroll
    for (int j = 0; j < 4; j++) {
        if ((&gm.x)[j] <= thrv) {
            int pos = atomicAdd(&s_gcnt[wly], 1);
            if (pos < GCAP) s_grp[wly][pos] = lane * 4 + j;
        }
    }
    __syncwarp();

    const int ng = s_gcnt[wly];
    const __half* orow = g_off + (size_t)r * N_COLS;

    if (ng <= GCAP) {
        // level 2: visit qualifying groups' offsets (32 per group, 1/lane)
        for (int gi = 0; gi < ng; gi++) {
            int col = s_grp[wly][gi] * 32 + lane;
            float v = xs + __half2float(orow[col]);
            if (v <= thrv) {
                int pos = atomicAdd(&s_cnt[wly], 1);
                if (pos < CAP) s_cand[wly][pos] = col;
            }
        }
        __syncwarp();
    } else {
        // fallback: scan all offsets
        #pragma unroll
        for (int it = 0; it < 16; it++) {
            const int v4 = it * 32 + lane;
            uint4 q = reinterpret_cast<const uint4*>(orow)[v4];
            const __half2* hp = reinterpret_cast<const __half2*>(&q);
            #pragma unroll
            for (int e = 0; e < 4; e++) {
                float2 f = __half22float2(hp[e]);
                if (xs + f.x <= thrv) {
                    int pos = atomicAdd(&s_cnt[wly], 1);
                    if (pos < CAP) s_cand[wly][pos] = v4 * 8 + e * 2;
                }
                if (xs + f.y <= thrv) {
                    int pos = atomicAdd(&s_cnt[wly], 1);
                    if (pos < CAP) s_cand[wly][pos] = v4 * 8 + e * 2 + 1;
                }
            }
        }
        __syncwarp();
    }

    const int nc = s_cnt[wly];
    unsigned long long best = 0xFFFFFFFFFFFFFFFFull;

    auto eval_col = [&](int col) {
        const float4* w4 =
            reinterpret_cast<const float4*>(w + (size_t)col * D_K + lane * 16);
        float d = 0.f;
        #pragma unroll
        for (int j = 0; j < 4; j++) {
            float4 a = xr[j], b = w4[j];
            d += a.x * b.x + a.y * b.y + a.z * b.z + a.w * b.w;
        }
        #pragma unroll
        for (int o = 16; o; o >>= 1) d += __shfl_xor_sync(0xffffffffu, d, o);
        float t = __fsub_rn(xs, __fmul_rn(2.0f, d));
        float v = fmaxf(__fadd_rn(t, g_wsq[col]), 0.0f);
        unsigned long long u = ((unsigned long long)__float_as_uint(v) << 32) |
                               (unsigned long long)(uint32_t)col;
        best = (u < best) ? u : best;
    };

    if (nc <= CAP) {
        for (int i = 0; i < nc; i++) eval_col(s_cand[wly][i]);
    } else {
        for (int c = 0; c < N_COLS; c++) eval_col(c);   // rare fallback
    }

    if (lane == 0) {
        int col = (int)(best & 0xFFFFFFFFull);
        float v = __uint_as_float((uint32_t)(best >> 32));
        out[2 * r]     = (float)(col >> 6);   // y = idx / 64
        out[2 * r + 1] = (float)(col & 63);   // x = idx % 64
        out[2 * B_ROWS + r] = sqrtf(v);
    }
}

extern "C" void kernel_launch(void* const* d_in, const int* in_sizes, int n_in,
                              void* d_out, int out_size) {
    const float* x = (const float*)d_in[0];   // inputs      (4096, 512)
    const float* w = (const float*)d_in[1];   // weights_map (64, 64, 512)
    float* out = (float*)d_out;

    static int smem_set = 0;
    if (!smem_set) {
        cudaFuncSetAttribute(som_mma_kernel,
                             cudaFuncAttributeMaxDynamicSharedMemorySize,
                             SMEM_BYTES);
        smem_set = 1;
    }

    {
        int warps = B_ROWS + N_COLS;
        int blocks = (warps * 32 + 255) / 256;   // exactly 1024
        prep_kernel<<<blocks, 256>>>(x, w);
    }
    {
        dim3 grid(B_ROWS / TILE_M, N_COLS / TILE_N);   // (32, 64) = 2048 CTAs
        som_mma_kernel<<<grid, 256, SMEM_BYTES>>>();
    }
    screen_kernel<<<B_ROWS / 8, 256>>>(x, w, out);
}

// round 17
// speedup vs baseline: 1.3086x; 1.3086x over previous
#include <cuda_runtime.h>
#include <cuda_fp16.h>
#include <math.h>
#include <stdint.h>

#define B_ROWS 4096
#define N_COLS 4096
#define D_K    512

#define TILE_M 128
#define TILE_N 128
#define KC     16
#define NCHUNK (D_K / KC)          // 32
#define NSTAGE 4

// smem geometry: rows of 16 halves padded to 24 halves (48 B) -> 16B-aligned
// cp.async segs AND conflict-free fragment LDS (stride 12 words).
#define RSH        24
#define ARR_B      (128 * RSH * 2) // 6144 bytes per operand array
#define STAGE_B    (2 * ARR_B)     // Ah, Bh = 12288
#define SMEM_BYTES (NSTAGE * STAGE_B) // 49152

#define CAP   32                   // candidates per row (warp-local)
#define GCAP  16                   // qualifying 32-col groups per row
#define NGRP  (N_COLS / 32)        // 128 groups per row

// ---------------- scratch (__device__ globals; no allocation allowed) -------
// g_whmax2/g_wlmax2: zero-initialized at module load; atomicMax with
// deterministic identical values every run -> idempotent, no re-init needed.
__device__ __half g_xh[B_ROWS * D_K];
__device__ __half g_wh[N_COLS * D_K];
__device__ float g_xsq[B_ROWS];
__device__ float g_wsq[N_COLS];
__device__ float g_xl2[B_ROWS];        // ||xl||^2 per row
__device__ float g_xh2[B_ROWS];        // ||xh||^2 per row
__device__ unsigned int g_whmax2;      // max_c ||wh_c||^2 (float bits)
__device__ unsigned int g_wlmax2;      // max_c ||wl_c||^2 (float bits)
__device__ unsigned long long g_best[B_ROWS];
__device__ __half g_off[(size_t)B_ROWS * N_COLS];   // 33.5 MB approx offsets
__device__ float g_gmin[B_ROWS * NGRP];             // 2 MB per-group minima

// ---------------- PTX helpers ----------------------------------------------
__device__ __forceinline__ uint32_t smem_u32(const void* p) {
    uint32_t a;
    asm("{ .reg .u64 t; cvta.to.shared.u64 t, %1; cvt.u32.u64 %0, t; }"
        : "=r"(a) : "l"(p));
    return a;
}
#define CP16(sa, ga) \
    asm volatile("cp.async.cg.shared.global [%0], [%1], 16;" \
                 :: "r"(sa), "l"(ga) : "memory")
#define CP_COMMIT()  asm volatile("cp.async.commit_group;" ::: "memory")
#define CP_WAIT2()   asm volatile("cp.async.wait_group 2;" ::: "memory")
#define CP_WAIT1()   asm volatile("cp.async.wait_group 1;" ::: "memory")
#define CP_WAIT0()   asm volatile("cp.async.wait_group 0;" ::: "memory")

__device__ __forceinline__ void mma16816(float* d, const uint32_t* a,
                                         const uint32_t* b) {
    asm volatile(
        "mma.sync.aligned.m16n8k16.row.col.f32.f16.f16.f32 "
        "{%0,%1,%2,%3}, {%4,%5,%6,%7}, {%8,%9}, {%0,%1,%2,%3};"
        : "+f"(d[0]), "+f"(d[1]), "+f"(d[2]), "+f"(d[3])
        : "r"(a[0]), "r"(a[1]), "r"(a[2]), "r"(a[3]), "r"(b[0]), "r"(b[1]));
}

// ---------------------------------------------------------------------------
// Kernel 0: fp16 hi plane + norms. One warp per row (x rows, then w rows).
// Blocks are homogeneous: blocks 0..511 = x rows, 512..1023 = w rows.
// w-blocks reduce their 8 warps' norm maxima in smem -> ONE atomicMax pair
// per block (8x fewer same-address L2 atomics).
// ---------------------------------------------------------------------------
__global__ void prep_kernel(const float* __restrict__ x,
                            const float* __restrict__ w) {
    __shared__ float s_sh[8], s_sl[8];
    int warp = (blockIdx.x * blockDim.x + threadIdx.x) >> 5;
    int wib  = (threadIdx.x >> 5);   // warp in block 0..7
    int lane = threadIdx.x & 31;
    if (warp >= B_ROWS + N_COLS) return;   // never taken with exact grid
    bool isx = (warp < B_ROWS);
    int row = isx ? warp : warp - B_ROWS;
    const float* src = isx ? (x + (size_t)row * D_K) : (w + (size_t)row * D_K);
    __half* dh = isx ? (g_xh + (size_t)row * D_K) : (g_wh + (size_t)row * D_K);

    float s = 0.f, sl = 0.f, sh = 0.f;
    #pragma unroll
    for (int k = lane * 4; k < D_K; k += 128) {
        float4 v = *reinterpret_cast<const float4*>(src + k);
        s += v.x * v.x + v.y * v.y + v.z * v.z + v.w * v.w;
        __half2 h01 = __floats2half2_rn(v.x, v.y);
        __half2 h23 = __floats2half2_rn(v.z, v.w);
        float2 f01 = __half22float2(h01);
        float2 f23 = __half22float2(h23);
        sh += f01.x * f01.x + f01.y * f01.y + f23.x * f23.x + f23.y * f23.y;
        float e0 = v.x - f01.x, e1 = v.y - f01.y;
        float e2 = v.z - f23.x, e3 = v.w - f23.y;
        sl += e0 * e0 + e1 * e1 + e2 * e2 + e3 * e3;
        __half2 hp[2] = { h01, h23 };
        *reinterpret_cast<uint2*>(dh + k) = *reinterpret_cast<uint2*>(hp);
    }
    #pragma unroll
    for (int o = 16; o; o >>= 1) {
        s  += __shfl_xor_sync(0xffffffffu, s, o);
        sl += __shfl_xor_sync(0xffffffffu, sl, o);
        sh += __shfl_xor_sync(0xffffffffu, sh, o);
    }
    if (lane == 0) {
        if (isx) {
            g_xsq[row] = s; g_xl2[row] = sl; g_xh2[row] = sh;
            g_best[row] = 0xFFFFFFFFFFFFFFFFull;
        } else {
            g_wsq[row] = s;
            s_sh[wib] = sh;
            s_sl[wib] = sl;
        }
    }
    if (!isx) {
        __syncthreads();
        if (threadIdx.x == 0) {
            float mh = s_sh[0], ml = s_sl[0];
            #pragma unroll
            for (int i = 1; i < 8; i++) {
                mh = fmaxf(mh, s_sh[i]);
                ml = fmaxf(ml, s_sl[i]);
            }
            atomicMax(&g_whmax2, __float_as_uint(mh));  // non-neg: bit order ok
            atomicMax(&g_wlmax2, __float_as_uint(ml));
        }
    }
}

// ---------------------------------------------------------------------------
// Kernel 1: fp16 hh-only GEMM (approx) + fp16 offset store + group minima.
// 1024-CTA grid (hardware work-stealing balances the 3.37 waves).
// CTA 128x128, 8 warps 2(m) x 4(n); 4-stage cp.async pipeline, prefetch
// distance 2 -> ONE __syncthreads per iteration is race-free (laggards read
// stage (i-1)%4 while loads target (i+2)%4; distance 3 mod 4 != 0).
// ---------------------------------------------------------------------------
__global__ __launch_bounds__(256, 2)
void som_mma_kernel() {
    extern __shared__ char smem[];
    const uint32_t sb = smem_u32(smem);
    const int tid  = threadIdx.x;
    const int wid  = tid >> 5;
    const int lane = tid & 31;
    const int gid  = lane >> 2;
    const int tg   = lane & 3;
    const int wm   = wid & 1;
    const int wn   = wid >> 1;
    const int m0 = blockIdx.x * TILE_M;
    const int n0 = blockIdx.y * TILE_N;

    float acc[4][4][4];
    #pragma unroll
    for (int mi = 0; mi < 4; mi++)
        #pragma unroll
        for (int ni = 0; ni < 4; ni++)
            #pragma unroll
            for (int c = 0; c < 4; c++) acc[mi][ni][c] = 0.f;

    const int lrow = tid >> 1, lseg = tid & 1;
    const uint32_t lso = (uint32_t)(lrow * (RSH * 2) + lseg * 16);

    auto load_chunk = [&](int kc) {
        const int kb = kc * KC;
        const uint32_t stage = sb + (uint32_t)((kc % NSTAGE) * STAGE_B);
        CP16(stage + 0 * ARR_B + lso,
             (const void*)(g_xh + (size_t)(m0 + lrow) * D_K + kb + lseg * 8));
        CP16(stage + 1 * ARR_B + lso,
             (const void*)(g_wh + (size_t)(n0 + lrow) * D_K + kb + lseg * 8));
        CP_COMMIT();
    };

    load_chunk(0); load_chunk(1);

    for (int i = 0; i < NCHUNK; i++) {
        if (i + 2 < NCHUNK) { load_chunk(i + 2); CP_WAIT2(); }
        else if (i + 1 < NCHUNK) { CP_WAIT1(); }
        else { CP_WAIT0(); }
        __syncthreads();

        const char* st = smem + (i % NSTAGE) * STAGE_B;
        const uint32_t* sAh = (const uint32_t*)(st);
        const uint32_t* sBh = (const uint32_t*)(st + ARR_B);
        const int RW = RSH / 2;  // 12

        uint32_t bh[4][2];
        #pragma unroll
        for (int ni = 0; ni < 4; ni++) {
            int r = (wn * 32 + ni * 8 + gid) * RW + tg;
            bh[ni][0] = sBh[r]; bh[ni][1] = sBh[r + 4];
        }
        #pragma unroll
        for (int mi = 0; mi < 4; mi++) {
            int r = (wm * 64 + mi * 16 + gid) * RW + tg;
            uint32_t ah[4];
            ah[0] = sAh[r];           ah[2] = sAh[r + 4];
            ah[1] = sAh[r + 8 * RW];  ah[3] = sAh[r + 8 * RW + 4];
            #pragma unroll
            for (int ni = 0; ni < 4; ni++)
                mma16816(acc[mi][ni], ah, bh[ni]);
        }
    }

    // ---- epilogue: offsets to fp16, per-group min, per-row approx argmin --
    float ws[4][2];
    #pragma unroll
    for (int ni = 0; ni < 4; ni++) {
        int col = n0 + wn * 32 + ni * 8 + tg * 2;
        ws[ni][0] = g_wsq[col];
        ws[ni][1] = g_wsq[col + 1];
    }
    const int grp = (n0 >> 5) + wn;   // this warp's 32-col group index

    #pragma unroll
    for (int mi = 0; mi < 4; mi++) {
        #pragma unroll
        for (int h = 0; h < 2; h++) {
            const int row = m0 + wm * 64 + mi * 16 + gid + h * 8;
            const float xs = g_xsq[row];
            unsigned long long best = 0xFFFFFFFFFFFFFFFFull;
            #pragma unroll
            for (int ni = 0; ni < 4; ni++) {
                const int col = n0 + wn * 32 + ni * 8 + tg * 2;
                float off0 = 0.f, off1 = 0.f;
                #pragma unroll
                for (int c = 0; c < 2; c++) {
                    const float dot = acc[mi][ni][h * 2 + c];
                    float off = ws[ni][c] - 2.0f * dot;
                    if (c == 0) off0 = off; else off1 = off;
                    float v = xs + off;
                    unsigned long long u =
                        ((unsigned long long)__float_as_uint(v) << 32) |
                        (unsigned long long)(uint32_t)(col + c);
                    best = (u < best) ? u : best;
                }
                *reinterpret_cast<__half2*>(
                    g_off + (size_t)row * N_COLS + col) =
                    __floats2half2_rn(off0, off1);
            }
            unsigned long long o;
            o = __shfl_xor_sync(0xffffffffu, best, 1); best = (o < best) ? o : best;
            o = __shfl_xor_sync(0xffffffffu, best, 2); best = (o < best) ? o : best;
            if (tg == 0) {
                // exact fp32 min value over this warp's 32 cols for this row
                g_gmin[row * NGRP + grp] =
                    __uint_as_float((uint32_t)(best >> 32));
                atomicMin(&g_best[row], best);
            }
        }
    }
}

// ---------------------------------------------------------------------------
// Kernel 2: hierarchical warp-per-row screen + exact fp32 rescreen + output.
// Independent loads (x row, gmin, norms) hoisted to the top to overlap the
// threshold dependency chain.
// ---------------------------------------------------------------------------
__global__ __launch_bounds__(256)
void screen_kernel(const float* __restrict__ x, const float* __restrict__ w,
                   float* __restrict__ out) {
    const int wly  = threadIdx.x >> 5;          // warp in block 0..7
    const int lane = threadIdx.x & 31;
    const int r    = blockIdx.x * 8 + wly;      // row

    __shared__ int s_cand[8][CAP];
    __shared__ int s_cnt[8];
    __shared__ int s_grp[8][GCAP];
    __shared__ int s_gcnt[8];

    if (lane == 0) { s_cnt[wly] = 0; s_gcnt[wly] = 0; }

    // ---- independent loads first (overlap the threshold chain) -----------
    const float* xrow = x + (size_t)r * D_K;
    float4 xr[4];
    #pragma unroll
    for (int j = 0; j < 4; j++)
        xr[j] = *reinterpret_cast<const float4*>(xrow + lane * 16 + j * 4);
    float4 gm = *reinterpret_cast<const float4*>(g_gmin + r * NGRP + lane * 4);
    const float xs = g_xsq[r];
    const float xl2 = g_xl2[r];
    const float xh2 = g_xh2[r];
    const unsigned long long brow = g_best[r];
    const float whm2 = __uint_as_float(g_whmax2);
    const float wlm2 = __uint_as_float(g_wlmax2);
    __syncwarp();

    // threshold in VALUE space (all lanes redundantly; broadcast loads)
    const float minv = __uint_as_float((uint32_t)(brow >> 32));
    const float whm = sqrtf(whm2), wlm = sqrtf(wlm2);
    const float xln = sqrtf(xl2),  xhn = sqrtf(xh2);
    // |v_exact - v_approx| <= 2*(xl.wh + xh.wl + xl.wl), 1.5x safety,
    // +0.02 covers fp16 offset-storage quantization.
    const float e_v = 3.0f * (xln * whm + xhn * wlm + xln * wlm) + 0.02f;
    const float thrv = minv + 2.0f * e_v;

    // level 1: scan 128 exact group minima (float4 per lane)
    #pragma unroll
    for (int j = 0; j < 4; j++) {
        if ((&gm.x)[j] <= thrv) {
            int pos = atomicAdd(&s_gcnt[wly], 1);
            if (pos < GCAP) s_grp[wly][pos] = lane * 4 + j;
        }
    }
    __syncwarp();

    const int ng = s_gcnt[wly];
    const __half* orow = g_off + (size_t)r * N_COLS;

    if (ng <= GCAP) {
        // level 2: visit qualifying groups' offsets (32 per group, 1/lane)
        for (int gi = 0; gi < ng; gi++) {
            int col = s_grp[wly][gi] * 32 + lane;
            float v = xs + __half2float(orow[col]);
            if (v <= thrv) {
                int pos = atomicAdd(&s_cnt[wly], 1);
                if (pos < CAP) s_cand[wly][pos] = col;
            }
        }
        __syncwarp();
    } else {
        // fallback: scan all offsets
        #pragma unroll
        for (int it = 0; it < 16; it++) {
            const int v4 = it * 32 + lane;
            uint4 q = reinterpret_cast<const uint4*>(orow)[v4];
            const __half2* hp = reinterpret_cast<const __half2*>(&q);
            #pragma unroll
            for (int e = 0; e < 4; e++) {
                float2 f = __half22float2(hp[e]);
                if (xs + f.x <= thrv) {
                    int pos = atomicAdd(&s_cnt[wly], 1);
                    if (pos < CAP) s_cand[wly][pos] = v4 * 8 + e * 2;
                }
                if (xs + f.y <= thrv) {
                    int pos = atomicAdd(&s_cnt[wly], 1);
                    if (pos < CAP) s_cand[wly][pos] = v4 * 8 + e * 2 + 1;
                }
            }
        }
        __syncwarp();
    }

    const int nc = s_cnt[wly];
    unsigned long long best = 0xFFFFFFFFFFFFFFFFull;

    auto eval_col = [&](int col) {
        const float4* w4 =
            reinterpret_cast<const float4*>(w + (size_t)col * D_K + lane * 16);
        float d = 0.f;
        #pragma unroll
        for (int j = 0; j < 4; j++) {
            float4 a = xr[j], b = w4[j];
            d += a.x * b.x + a.y * b.y + a.z * b.z + a.w * b.w;
        }
        #pragma unroll
        for (int o = 16; o; o >>= 1) d += __shfl_xor_sync(0xffffffffu, d, o);
        float t = __fsub_rn(xs, __fmul_rn(2.0f, d));
        float v = fmaxf(__fadd_rn(t, g_wsq[col]), 0.0f);
        unsigned long long u = ((unsigned long long)__float_as_uint(v) << 32) |
                               (unsigned long long)(uint32_t)col;
        best = (u < best) ? u : best;
    };

    if (nc <= CAP) {
        for (int i = 0; i < nc; i++) eval_col(s_cand[wly][i]);
    } else {
        for (int c = 0; c < N_COLS; c++) eval_col(c);   // rare fallback
    }

    if (lane == 0) {
        int col = (int)(best & 0xFFFFFFFFull);
        float v = __uint_as_float((uint32_t)(best >> 32));
        out[2 * r]     = (float)(col >> 6);   // y = idx / 64
        out[2 * r + 1] = (float)(col & 63);   // x = idx % 64
        out[2 * B_ROWS + r] = sqrtf(v);
    }
}

extern "C" void kernel_launch(void* const* d_in, const int* in_sizes, int n_in,
                              void* d_out, int out_size) {
    const float* x = (const float*)d_in[0];   // inputs      (4096, 512)
    const float* w = (const float*)d_in[1];   // weights_map (64, 64, 512)
    float* out = (float*)d_out;

    static int smem_set = 0;
    if (!smem_set) {
        cudaFuncSetAttribute(som_mma_kernel,
                             cudaFuncAttributeMaxDynamicSharedMemorySize,
                             SMEM_BYTES);
        smem_set = 1;
    }

    {
        int warps = B_ROWS + N_COLS;
        int blocks = (warps * 32 + 255) / 256;   // exactly 1024
        prep_kernel<<<blocks, 256>>>(x, w);
    }
    {
        dim3 grid(B_ROWS / TILE_M, N_COLS / TILE_N);   // (32, 32)
        som_mma_kernel<<<grid, 256, SMEM_BYTES>>>();
    }
    screen_kernel<<<B_ROWS / 8, 256>>>(x, w, out);
}